// round 8
// baseline (speedup 1.0000x reference)
#include <cuda_runtime.h>
#include <math.h>

#define N 2048
#define IN_DIM 128
#define OUT_DIM 32
#define GROWS 64                      // rows per block
#define WROWS 8                       // rows per warp
#define NWARPS 8
#define TABSZ 1024
#define JSPLIT 16
#define JCHUNK (N / JSPLIT)           // 128 j's per block
#define NBATCH (JCHUNK / 32)          // 4 batches of 32 j's (all warps together)
#define NGROUPS (N / GROWS)           // 32 row-groups

#define PREP_BLKS (N / 4)                        // 512 (4 rows/block, split-K)
#define TAB_BLKS  ((TABSZ + 1 + 7) / 8)          // 129 (8 q's per block)

// Scratch (allocation-free rule: __device__ globals)
__device__ float g_z[N * OUT_DIM];
__device__ float g_src[N];
__device__ float g_dst[N];
__device__ float g_val[TABSZ + 1];
__device__ float g_maxdst = -1e30f;   // reset by last finisher (graph-safe)
__device__ float g_maxg   = -1e30f;
__device__ float g_pl[N * JSPLIT];               // partial softmax denominators
__device__ float g_pa[N * JSPLIT * OUT_DIM];     // partial att@z accumulators
__device__ unsigned g_cnt[NGROUPS];              // zero-init; reset by finisher
__device__ unsigned g_done = 0;                  // reset by last finisher

__device__ __forceinline__ float atomicMaxFloat(float* addr, float value) {
    return (value >= 0.f)
        ? __int_as_float(atomicMax((int*)addr, __float_as_int(value)))
        : __uint_as_float(atomicMin((unsigned*)addr, __float_as_uint(value)));
}

// ---------------------------------------------------------------------------
// Fused prologue. Blocks [0,512): z = feat@W (split-K: 2 warps per row,
// 64 dims each, W staged in smem), src, dst (+ dst max atomic).
// Blocks [512,641): e_time lookup table (+ table max atomic).
// ---------------------------------------------------------------------------
__global__ void __launch_bounds__(256)
prep_kernel(const float* __restrict__ feat,
            const float* __restrict__ a,
            const float* __restrict__ W,
            const int*   __restrict__ te,
            const float* __restrict__ bf) {
    const int warp = threadIdx.x >> 5;
    const int lane = threadIdx.x & 31;
    __shared__ float s_W[IN_DIM * OUT_DIM];      // 16 KB
    __shared__ float s_part[4][2][OUT_DIM];
    __shared__ float s_red[8];

    if (blockIdx.x < PREP_BLKS) {
        const float4* wsrc = (const float4*)W;
        float4*       wdst = (float4*)s_W;
#pragma unroll
        for (int t = 0; t < 4; ++t)
            wdst[threadIdx.x + 256 * t] = wsrc[threadIdx.x + 256 * t];
        __syncthreads();

        const int r    = warp >> 1;              // 0..3  row within block
        const int half = warp & 1;               // 0..1  K-split
        const int i    = blockIdx.x * 4 + r;
        const float4* f4 = (const float4*)(feat + i * IN_DIM) + half * 16;
        const float*  Wm = s_W + half * 64 * OUT_DIM;
        float a0 = 0.f, a1 = 0.f, a2 = 0.f, a3 = 0.f;
#pragma unroll
        for (int d4 = 0; d4 < 16; ++d4) {
            float4 f = f4[d4];                   // uniform (broadcast)
            a0 = fmaf(f.x, Wm[(d4 * 4 + 0) * OUT_DIM + lane], a0);
            a1 = fmaf(f.y, Wm[(d4 * 4 + 1) * OUT_DIM + lane], a1);
            a2 = fmaf(f.z, Wm[(d4 * 4 + 2) * OUT_DIM + lane], a2);
            a3 = fmaf(f.w, Wm[(d4 * 4 + 3) * OUT_DIM + lane], a3);
        }
        s_part[r][half][lane] = (a0 + a1) + (a2 + a3);
        __syncthreads();

        if (warp < 4) {
            const int i2 = blockIdx.x * 4 + warp;
            float acc = s_part[warp][0][lane] + s_part[warp][1][lane];
            g_z[i2 * OUT_DIM + lane] = acc;
            float s = acc * a[lane];
            float t = acc * a[OUT_DIM + lane];
#pragma unroll
            for (int o = 16; o > 0; o >>= 1) {
                s += __shfl_xor_sync(0xffffffffu, s, o);
                t += __shfl_xor_sync(0xffffffffu, t, o);
            }
            if (lane == 0) { g_src[i2] = s; g_dst[i2] = t; s_red[warp] = t; }
        }
        __syncthreads();
        if (threadIdx.x == 0) {
            float md = fmaxf(fmaxf(s_red[0], s_red[1]),
                             fmaxf(s_red[2], s_red[3]));
            atomicMaxFloat(&g_maxdst, md);
        }
    } else {
        const int q = (blockIdx.x - PREP_BLKS) * 8 + warp;
        float v = -1e30f;
        if (q <= TABSZ) {
            int ti = *te;
            float T = (ti > -1000000 && ti < 1000000) ? (float)ti
                                                      : __int_as_float(ti);
            float tsv = (float)q / (float)TABSZ;
            float dt  = T - tsv;
            float th  = dt * bf[lane];
            v = a[2 * lane] * sinf(th) + a[2 * lane + 1] * cosf(th);
#pragma unroll
            for (int o = 16; o > 0; o >>= 1)
                v += __shfl_xor_sync(0xffffffffu, v, o);
            if (lane == 0) g_val[q] = v;
        }
        if (lane == 0) s_red[warp] = v;
        __syncthreads();
        if (threadIdx.x == 0) {
            float mg = s_red[0];
#pragma unroll
            for (int w = 1; w < 8; ++w) mg = fmaxf(mg, s_red[w]);
            atomicMaxFloat(&g_maxg, mg);
        }
    }
}

// ---------------------------------------------------------------------------
// Fused attention + epilogue. grid = (NGROUPS, JSPLIT).
// Block = 64 rows x 128 j. ALL warps walk the SAME j-batches (warp w owns
// rows i0+8w..+7): z loads become L1 broadcast hits after the first warp.
// No cross-warp combine needed (acc is per-warp-exclusive). Lane-parallel
// scores with fixed softmax shift; PV via smem-staged p + LDS.128 with
// 8-deep explicit zv load groups. Finisher via acq_rel atomic.
// ---------------------------------------------------------------------------
__global__ void __launch_bounds__(256, 3)
attn_kernel(const int*   __restrict__ adj,
            const float* __restrict__ ts,
            const float* __restrict__ gamma,
            const float* __restrict__ beta,
            float*       __restrict__ out) {
    __shared__ float2 s_tab[TABSZ];                       // 8 KB
    __shared__ float2 s_row[GROWS];                       // (src, m) per row
    __shared__ float  sm_p[NWARPS][32][WROWS];            // 8 KB
    __shared__ unsigned s_flag;

    const int i0    = blockIdx.x * GROWS;
    const int split = blockIdx.y;
    const int jbase = split * JCHUNK;
    const int warp  = threadIdx.x >> 5;
    const int lane  = threadIdx.x & 31;
    const int irow0 = i0 + warp * WROWS;      // this warp's first row

    for (int q = threadIdx.x; q < TABSZ; q += 256)
        s_tab[q] = make_float2(g_val[q], g_val[q + 1]);
    if (threadIdx.x < GROWS) {
        float s = g_src[i0 + threadIdx.x];
        float U = s + g_maxdst + g_maxg;
        s_row[threadIdx.x] = make_float2(s, fmaxf(U, 0.05f * U));
    }
    __syncthreads();

    float l[WROWS], acc[WROWS];
#pragma unroll
    for (int r = 0; r < WROWS; ++r) { l[r] = 0.f; acc[r] = 0.f; }

    // Prefetch batch 0 (adj/ts/dst) into registers.
    int   av[WROWS];
    float tv[WROWS];
    float dstj;
    {
        const int j = jbase + lane;
        dstj = g_dst[j];
#pragma unroll
        for (int r = 0; r < WROWS; ++r) {
            av[r] = adj[(irow0 + r) * N + j];
            tv[r] = ts [(irow0 + r) * N + j];
        }
    }

#pragma unroll
    for (int bb = 0; bb < NBATCH; ++bb) {
        // Prefetch next batch (clamped; unused regs on last iteration).
        const int sb = (bb + 1 < NBATCH) ? bb + 1 : bb;
        const int jn = jbase + sb * 32 + lane;
        float ndstj = g_dst[jn];
        int   nav[WROWS];
        float ntv[WROWS];
#pragma unroll
        for (int r = 0; r < WROWS; ++r) {
            nav[r] = adj[(irow0 + r) * N + jn];
            ntv[r] = ts [(irow0 + r) * N + jn];
        }

        // Score for current batch (registers already resident).
        float p[WROWS];
#pragma unroll
        for (int r = 0; r < WROWS; ++r) {
            float2 sr = s_row[warp * WROWS + r];   // (src, m) broadcast LDS
            float qf = tv[r] * (float)TABSZ;       // ts in [0,1)
            int   qi = __float2int_rz(qf);
            float fr = qf - (float)qi;
            float2 tt = s_tab[qi];
            float g  = fmaf(fr, tt.y - tt.x, tt.x);
            float e  = sr.x + dstj + g;
            e = fmaxf(e, 0.05f * e);               // leaky relu
            e = (av[r] > 0) ? (e - sr.y) : -1e30f; // mask -> p = 0
            p[r] = __expf(e);
            l[r] += p[r];
        }
        // Stage p tile to smem: 2x STS.128 per lane
        float4* pd = (float4*)&sm_p[warp][lane][0];
        pd[0] = make_float4(p[0], p[1], p[2], p[3]);
        pd[1] = make_float4(p[4], p[5], p[6], p[7]);
        __syncwarp();

        // PV: all warps read the SAME z stream -> L1 broadcast hits.
        const float* zb = g_z + (jbase + bb * 32) * OUT_DIM + lane;
#pragma unroll
        for (int grp = 0; grp < 4; ++grp) {
            float zv[8];
#pragma unroll
            for (int u = 0; u < 8; ++u)            // 8 loads in flight
                zv[u] = zb[(grp * 8 + u) * OUT_DIM];
#pragma unroll
            for (int u = 0; u < 8; ++u) {
                const float4* ps = (const float4*)&sm_p[warp][grp * 8 + u][0];
                float4 p03 = ps[0];                // broadcast LDS.128
                float4 p47 = ps[1];
                acc[0] = fmaf(p03.x, zv[u], acc[0]);
                acc[1] = fmaf(p03.y, zv[u], acc[1]);
                acc[2] = fmaf(p03.z, zv[u], acc[2]);
                acc[3] = fmaf(p03.w, zv[u], acc[3]);
                acc[4] = fmaf(p47.x, zv[u], acc[4]);
                acc[5] = fmaf(p47.y, zv[u], acc[5]);
                acc[6] = fmaf(p47.z, zv[u], acc[6]);
                acc[7] = fmaf(p47.w, zv[u], acc[7]);
            }
        }
        __syncwarp();

        // Rotate prefetch registers.
        dstj = ndstj;
#pragma unroll
        for (int r = 0; r < WROWS; ++r) { av[r] = nav[r]; tv[r] = ntv[r]; }
    }

    // Per-warp partials: acc[r][lane] is complete for this chunk; l needs
    // a lane reduction. Write straight to global (no cross-warp combine).
#pragma unroll
    for (int r = 0; r < WROWS; ++r) {
        float lv = l[r];
#pragma unroll
        for (int o = 16; o > 0; o >>= 1)
            lv += __shfl_xor_sync(0xffffffffu, lv, o);
        const int i = irow0 + r;
        g_pa[(i * JSPLIT + split) * OUT_DIM + lane] = acc[r];
        if (lane == 0) g_pl[i * JSPLIT + split] = lv;
    }
    __syncthreads();   // all partial writes done before the release-arrive

    // Elect the last split-block of this row-group as finisher (acq_rel).
    if (threadIdx.x == 0) {
        unsigned old;
        asm volatile("atom.add.acq_rel.gpu.u32 %0, [%1], 1;"
                     : "=r"(old)
                     : "l"(&g_cnt[blockIdx.x])
                     : "memory");
        s_flag = (old == JSPLIT - 1) ? 1u : 0u;
    }
    __syncthreads();

    if (s_flag) {
#pragma unroll
        for (int r = 0; r < WROWS; ++r) {
            const int i = irow0 + r;
            float A = 0.f, L = 0.f;
#pragma unroll
            for (int s = 0; s < JSPLIT; ++s) {
                A += g_pa[(i * JSPLIT + s) * OUT_DIM + lane];
                L += g_pl[i * JSPLIT + s];
            }
            float temp = A / L + g_z[i * OUT_DIM + lane];

            float mu = temp;
#pragma unroll
            for (int o = 16; o > 0; o >>= 1)
                mu += __shfl_xor_sync(0xffffffffu, mu, o);
            mu *= (1.0f / OUT_DIM);
            float d = temp - mu;
            float v = d * d;
#pragma unroll
            for (int o = 16; o > 0; o >>= 1)
                v += __shfl_xor_sync(0xffffffffu, v, o);
            v *= (1.0f / OUT_DIM);
            out[i * OUT_DIM + lane] =
                d * rsqrtf(v + 1e-6f) * gamma[lane] + beta[lane];
        }

        if (threadIdx.x == 0) {
            g_cnt[blockIdx.x] = 0;       // re-arm for next replay
            if (atomicAdd(&g_done, 1) == NGROUPS - 1) {
                g_maxdst = -1e30f;       // all blocks have read MB by now
                g_maxg   = -1e30f;
                g_done   = 0;
            }
        }
    }
}

// ---------------------------------------------------------------------------
extern "C" void kernel_launch(void* const* d_in, const int* in_sizes, int n_in,
                              void* d_out, int out_size) {
    const float* feat = (const float*)d_in[0];   // (2048,128) f32
    const int*   adj  = (const int*)  d_in[1];   // (2048,2048) i32
    const float* ts   = (const float*)d_in[2];   // (2048,2048) f32
    const float* a    = (const float*)d_in[3];   // (64,1) f32
    const int*   te   = (const int*)  d_in[4];   // scalar int
    const float* W    = (const float*)d_in[5];   // (128,32) f32
    const float* bf   = (const float*)d_in[6];   // (32,) f32
    const float* gam  = (const float*)d_in[7];   // (32,) f32
    const float* bet  = (const float*)d_in[8];   // (32,) f32
    float* out = (float*)d_out;                  // (2048,32) f32

    prep_kernel<<<PREP_BLKS + TAB_BLKS, 256>>>(feat, a, W, te, bf);
    dim3 grid(NGROUPS, JSPLIT);
    attn_kernel<<<grid, 256>>>(adj, ts, gam, bet, out);
}

// round 9
// speedup vs baseline: 1.2341x; 1.2341x over previous
#include <cuda_runtime.h>
#include <math.h>

#define N 2048
#define IN_DIM 128
#define OUT_DIM 32
#define ROWS 8
#define NWARPS 8
#define TABSZ 1024
#define JSPLIT 4
#define JCHUNK (N / JSPLIT)          // 512 j's per block
#define NBATCH (JCHUNK / 32)         // 16 batches; each warp owns 2
#define NGROUPS (N / ROWS)           // 256 row-groups

#define PREP_BLKS (N / 4)                        // 512 (4 rows/block, split-K)
#define TAB_BLKS  ((TABSZ + 1 + 7) / 8)          // 129 (8 q's per block)

// Scratch (allocation-free rule: __device__ globals)
__device__ float g_z[N * OUT_DIM];
__device__ float g_src[N];
__device__ float g_dst[N];
__device__ float g_val[TABSZ + 1];
__device__ float g_maxdst = -1e30f;   // reset by combine (graph-safe)
__device__ float g_maxg   = -1e30f;
__device__ float g_pl[N * JSPLIT];               // partial softmax denominators
__device__ float g_pa[N * JSPLIT * OUT_DIM];     // partial att@z accumulators

__device__ __forceinline__ float atomicMaxFloat(float* addr, float value) {
    return (value >= 0.f)
        ? __int_as_float(atomicMax((int*)addr, __float_as_int(value)))
        : __uint_as_float(atomicMin((unsigned*)addr, __float_as_uint(value)));
}

__device__ __forceinline__ void cp16(void* smem, const void* gmem) {
    unsigned s = (unsigned)__cvta_generic_to_shared(smem);
    asm volatile("cp.async.ca.shared.global [%0], [%1], 16;" :: "r"(s), "l"(gmem));
}
#define CP_COMMIT() asm volatile("cp.async.commit_group;")
#define CP_WAIT(n)  asm volatile("cp.async.wait_group %0;" :: "n"(n))

// ---------------------------------------------------------------------------
// Fused prologue. Blocks [0,512): z = feat@W (split-K: 2 warps per row,
// W staged in smem), src, dst (+ dst max atomic).
// Blocks [512,641): e_time lookup table (+ table max atomic).
// ---------------------------------------------------------------------------
__global__ void __launch_bounds__(256)
prep_kernel(const float* __restrict__ feat,
            const float* __restrict__ a,
            const float* __restrict__ W,
            const int*   __restrict__ te,
            const float* __restrict__ bf) {
    const int warp = threadIdx.x >> 5;
    const int lane = threadIdx.x & 31;
    __shared__ float s_W[IN_DIM * OUT_DIM];      // 16 KB
    __shared__ float s_part[4][2][OUT_DIM];
    __shared__ float s_red[8];

    if (blockIdx.x < PREP_BLKS) {
        const float4* wsrc = (const float4*)W;
        float4*       wdst = (float4*)s_W;
#pragma unroll
        for (int t = 0; t < 4; ++t)
            wdst[threadIdx.x + 256 * t] = wsrc[threadIdx.x + 256 * t];
        __syncthreads();

        const int r    = warp >> 1;              // 0..3  row within block
        const int half = warp & 1;               // 0..1  K-split
        const int i    = blockIdx.x * 4 + r;
        const float4* f4 = (const float4*)(feat + i * IN_DIM) + half * 16;
        const float*  Wm = s_W + half * 64 * OUT_DIM;
        float a0 = 0.f, a1 = 0.f, a2 = 0.f, a3 = 0.f;
#pragma unroll
        for (int d4 = 0; d4 < 16; ++d4) {
            float4 f = f4[d4];                   // uniform (broadcast)
            a0 = fmaf(f.x, Wm[(d4 * 4 + 0) * OUT_DIM + lane], a0);
            a1 = fmaf(f.y, Wm[(d4 * 4 + 1) * OUT_DIM + lane], a1);
            a2 = fmaf(f.z, Wm[(d4 * 4 + 2) * OUT_DIM + lane], a2);
            a3 = fmaf(f.w, Wm[(d4 * 4 + 3) * OUT_DIM + lane], a3);
        }
        s_part[r][half][lane] = (a0 + a1) + (a2 + a3);
        __syncthreads();

        if (warp < 4) {
            const int i2 = blockIdx.x * 4 + warp;
            float acc = s_part[warp][0][lane] + s_part[warp][1][lane];
            g_z[i2 * OUT_DIM + lane] = acc;
            float s = acc * a[lane];
            float t = acc * a[OUT_DIM + lane];
#pragma unroll
            for (int o = 16; o > 0; o >>= 1) {
                s += __shfl_xor_sync(0xffffffffu, s, o);
                t += __shfl_xor_sync(0xffffffffu, t, o);
            }
            if (lane == 0) { g_src[i2] = s; g_dst[i2] = t; s_red[warp] = t; }
        }
        __syncthreads();
        if (threadIdx.x == 0) {
            float md = fmaxf(fmaxf(s_red[0], s_red[1]),
                             fmaxf(s_red[2], s_red[3]));
            atomicMaxFloat(&g_maxdst, md);
        }
    } else {
        const int q = (blockIdx.x - PREP_BLKS) * 8 + warp;
        float v = -1e30f;
        if (q <= TABSZ) {
            int ti = *te;
            float T = (ti > -1000000 && ti < 1000000) ? (float)ti
                                                      : __int_as_float(ti);
            float tsv = (float)q / (float)TABSZ;
            float dt  = T - tsv;
            float th  = dt * bf[lane];
            v = a[2 * lane] * sinf(th) + a[2 * lane + 1] * cosf(th);
#pragma unroll
            for (int o = 16; o > 0; o >>= 1)
                v += __shfl_xor_sync(0xffffffffu, v, o);
            if (lane == 0) g_val[q] = v;
        }
        if (lane == 0) s_red[warp] = v;
        __syncthreads();
        if (threadIdx.x == 0) {
            float mg = s_red[0];
#pragma unroll
            for (int w = 1; w < 8; ++w) mg = fmaxf(mg, s_red[w]);
            atomicMaxFloat(&g_maxg, mg);
        }
    }
}

// ---------------------------------------------------------------------------
// Fused attention, grid = (NGROUPS, JSPLIT). R5 skeleton + cp.async staging:
// each warp owns batches {warp, warp+8}; both batches' adj/ts are staged to
// smem via LDGSTS at kernel start (2 commit groups), overlapped with the
// table preload. Score reads LDS (29cyc) instead of LDG (577cyc).
// Lane-parallel scores with fixed softmax shift; PV via smem-staged p +
// broadcast LDS.128 with 8-deep grouped zv loads.
// ---------------------------------------------------------------------------
__global__ void __launch_bounds__(256)
attn_kernel(const int*   __restrict__ adj,
            const float* __restrict__ ts) {
    __shared__ float2 s_tab[TABSZ];                       // 8 KB
    __shared__ float2 s_row[ROWS];                        // (src, m) per row
    __shared__ __align__(16) float sm_p[NWARPS][32][ROWS];// 8 KB
    __shared__ float sm_l[ROWS][NWARPS];
    __shared__ float sm_a[ROWS][NWARPS][OUT_DIM];         // 8 KB
    __shared__ __align__(16) int   s_adj[NWARPS][2][ROWS * 32];  // 16 KB
    __shared__ __align__(16) float s_ts [NWARPS][2][ROWS * 32];  // 16 KB

    const int i0    = blockIdx.x * ROWS;
    const int split = blockIdx.y;
    const int jbase = split * JCHUNK;
    const int warp  = threadIdx.x >> 5;
    const int lane  = threadIdx.x & 31;

    // Issue cp.async for BOTH of this warp's batches (adj+ts), two groups.
    // 64 segments of 16B per array per batch; 32 lanes -> 2 each.
#pragma unroll
    for (int t = 0; t < 2; ++t) {
        const int jb = jbase + (warp + t * NWARPS) * 32;
#pragma unroll
        for (int k = 0; k < 2; ++k) {
            int seg = k * 32 + lane;
            int r = seg >> 3;              // 0..7
            int c = (seg & 7) * 4;         // 0,4,..,28
            cp16(&s_adj[warp][t][r * 32 + c], &adj[(i0 + r) * N + jb + c]);
            cp16(&s_ts [warp][t][r * 32 + c], &ts [(i0 + r) * N + jb + c]);
        }
        CP_COMMIT();
    }

    // dst for both batches (tiny, L2-hot after first blocks touch it).
    float dstj0 = g_dst[jbase + warp * 32 + lane];
    float dstj1 = g_dst[jbase + (warp + NWARPS) * 32 + lane];

    // Table preload overlaps the in-flight LDGSTS.
    for (int q = threadIdx.x; q < TABSZ; q += 256)
        s_tab[q] = make_float2(g_val[q], g_val[q + 1]);
    if (threadIdx.x < ROWS) {
        float s = g_src[i0 + threadIdx.x];
        float U = s + g_maxdst + g_maxg;
        s_row[threadIdx.x] = make_float2(s, fmaxf(U, 0.05f * U));
    }
    __syncthreads();

    float l[ROWS], acc[ROWS];
#pragma unroll
    for (int r = 0; r < ROWS; ++r) { l[r] = 0.f; acc[r] = 0.f; }

#pragma unroll
    for (int t = 0; t < 2; ++t) {
        if (t == 0) { CP_WAIT(1); } else { CP_WAIT(0); }
        __syncwarp();
        const int bb   = warp + t * NWARPS;
        const float dstj = (t == 0) ? dstj0 : dstj1;

        // Score: lane = j within batch; adj/ts from smem.
        float p[ROWS];
#pragma unroll
        for (int r = 0; r < ROWS; ++r) {
            float2 sr = s_row[r];                  // (src, m) broadcast LDS
            int   av  = s_adj[warp][t][r * 32 + lane];
            float tv  = s_ts [warp][t][r * 32 + lane];
            float qf = tv * (float)TABSZ;          // ts in [0,1)
            int   qi = __float2int_rz(qf);
            float fr = qf - (float)qi;
            float2 tt = s_tab[qi];
            float g  = fmaf(fr, tt.y - tt.x, tt.x);
            float e  = sr.x + dstj + g;
            e = fmaxf(e, 0.05f * e);               // leaky relu
            e = (av > 0) ? (e - sr.y) : -1e30f;    // mask -> p = 0
            p[r] = __expf(e);
            l[r] += p[r];
        }
        // Stage p tile to smem: 2x STS.128 per lane
        float4* pd = (float4*)&sm_p[warp][lane][0];
        pd[0] = make_float4(p[0], p[1], p[2], p[3]);
        pd[1] = make_float4(p[4], p[5], p[6], p[7]);
        __syncwarp();

        // PV with 8-deep grouped zv loads for MLP.
        const float* zb = g_z + (jbase + bb * 32) * OUT_DIM + lane;
#pragma unroll
        for (int grp = 0; grp < 4; ++grp) {
            float zv[8];
#pragma unroll
            for (int u = 0; u < 8; ++u)
                zv[u] = zb[(grp * 8 + u) * OUT_DIM];
#pragma unroll
            for (int u = 0; u < 8; ++u) {
                const float4* ps = (const float4*)&sm_p[warp][grp * 8 + u][0];
                float4 p03 = ps[0];                // broadcast LDS.128
                float4 p47 = ps[1];
                acc[0] = fmaf(p03.x, zv[u], acc[0]);
                acc[1] = fmaf(p03.y, zv[u], acc[1]);
                acc[2] = fmaf(p03.z, zv[u], acc[2]);
                acc[3] = fmaf(p03.w, zv[u], acc[3]);
                acc[4] = fmaf(p47.x, zv[u], acc[4]);
                acc[5] = fmaf(p47.y, zv[u], acc[5]);
                acc[6] = fmaf(p47.z, zv[u], acc[6]);
                acc[7] = fmaf(p47.w, zv[u], acc[7]);
            }
        }
        __syncwarp();
    }

    // Reduce l within warp; stash partials for cross-warp combine.
#pragma unroll
    for (int r = 0; r < ROWS; ++r) {
        float lv = l[r];
#pragma unroll
        for (int o = 16; o > 0; o >>= 1)
            lv += __shfl_xor_sync(0xffffffffu, lv, o);
        if (lane == 0) sm_l[r][warp] = lv;
        sm_a[r][warp][lane] = acc[r];
    }
    __syncthreads();

    // Warp r writes partial for row i0+r, this split.
    {
        const int r = warp;
        const int i = i0 + r;
        float L = 0.f, A = 0.f;
#pragma unroll
        for (int w = 0; w < NWARPS; ++w) {
            L += sm_l[r][w];
            A += sm_a[r][w][lane];
        }
        g_pa[(i * JSPLIT + split) * OUT_DIM + lane] = A;
        if (lane == 0) g_pl[i * JSPLIT + split] = L;
    }
}

// ---------------------------------------------------------------------------
// Combine partials + residual + layernorm. One warp per row.
// Also resets the max cells for the next graph replay.
// ---------------------------------------------------------------------------
__global__ void __launch_bounds__(256)
combine_kernel(const float* __restrict__ gamma,
               const float* __restrict__ beta,
               float*       __restrict__ out) {
    const int warp = threadIdx.x >> 5;
    const int lane = threadIdx.x & 31;
    const int i = blockIdx.x * 8 + warp;

    float A = 0.f, L = 0.f;
#pragma unroll
    for (int s = 0; s < JSPLIT; ++s) {
        A += g_pa[(i * JSPLIT + s) * OUT_DIM + lane];
        L += g_pl[i * JSPLIT + s];
    }
    float temp = A / L + g_z[i * OUT_DIM + lane];

    float mu = temp;
#pragma unroll
    for (int o = 16; o > 0; o >>= 1) mu += __shfl_xor_sync(0xffffffffu, mu, o);
    mu *= (1.0f / OUT_DIM);
    float d = temp - mu;
    float v = d * d;
#pragma unroll
    for (int o = 16; o > 0; o >>= 1) v += __shfl_xor_sync(0xffffffffu, v, o);
    v *= (1.0f / OUT_DIM);
    out[i * OUT_DIM + lane] = d * rsqrtf(v + 1e-6f) * gamma[lane] + beta[lane];

    if (blockIdx.x == 0 && threadIdx.x == 0) {
        g_maxdst = -1e30f;      // reset for next replay (deterministic)
        g_maxg   = -1e30f;
    }
}

// ---------------------------------------------------------------------------
extern "C" void kernel_launch(void* const* d_in, const int* in_sizes, int n_in,
                              void* d_out, int out_size) {
    const float* feat = (const float*)d_in[0];   // (2048,128) f32
    const int*   adj  = (const int*)  d_in[1];   // (2048,2048) i32
    const float* ts   = (const float*)d_in[2];   // (2048,2048) f32
    const float* a    = (const float*)d_in[3];   // (64,1) f32
    const int*   te   = (const int*)  d_in[4];   // scalar int
    const float* W    = (const float*)d_in[5];   // (128,32) f32
    const float* bf   = (const float*)d_in[6];   // (32,) f32
    const float* gam  = (const float*)d_in[7];   // (32,) f32
    const float* bet  = (const float*)d_in[8];   // (32,) f32
    float* out = (float*)d_out;                  // (2048,32) f32

    prep_kernel<<<PREP_BLKS + TAB_BLKS, 256>>>(feat, a, W, te, bf);
    dim3 grid(NGROUPS, JSPLIT);
    attn_kernel<<<grid, 256>>>(adj, ts);
    combine_kernel<<<N / 8, 256>>>(gam, bet, out);
}

// round 10
// speedup vs baseline: 1.3497x; 1.0937x over previous
#include <cuda_runtime.h>
#include <math.h>

#define N 2048
#define IN_DIM 128
#define OUT_DIM 32
#define ROWS 8
#define NWARPS 8
#define TABSZ 1024
#define JSPLIT 4
#define JCHUNK (N / JSPLIT)          // 512 j's per block
#define NBATCH (JCHUNK / 32)         // 16 batches of 32 j's
#define NGROUPS (N / ROWS)           // 256 row-groups

#define PREP_BLKS (N / 16)                       // 128 (16 rows/block)
#define TAB_BLKS  ((TABSZ + 1 + 7) / 8)          // 129 (8 q's per block)

// Scratch (allocation-free rule: __device__ globals)
__device__ float g_z[N * OUT_DIM];
__device__ float g_src[N];
__device__ float g_dst[N];
__device__ float g_val[TABSZ + 1];
__device__ float g_maxdst = -1e30f;   // reset by combine each run (graph-safe)
__device__ float g_maxg   = -1e30f;
__device__ float g_pl[N * JSPLIT];               // partial softmax denominators
__device__ float g_pa[N * JSPLIT * OUT_DIM];     // partial att@z accumulators

__device__ __forceinline__ float atomicMaxFloat(float* addr, float value) {
    return (value >= 0.f)
        ? __int_as_float(atomicMax((int*)addr, __float_as_int(value)))
        : __uint_as_float(atomicMin((unsigned*)addr, __float_as_uint(value)));
}

__device__ __forceinline__ void cp16(void* smem, const void* gmem) {
    unsigned s = (unsigned)__cvta_generic_to_shared(smem);
    asm volatile("cp.async.ca.shared.global [%0], [%1], 16;" :: "r"(s), "l"(gmem));
}
#define CP_COMMIT() asm volatile("cp.async.commit_group;")
#define CP_WAIT0()  asm volatile("cp.async.wait_group 0;")

// ---------------------------------------------------------------------------
// Fused prologue. Blocks [0,128): z = feat@W for 16 rows/block. W (16KB) and
// the feat tile (8KB) are cp.async-staged once per block; each warp computes
// 2 rows x 32 cols from smem (W at bank=lane, conflict-free; feat broadcast
// LDS.128; W value reused across both rows). Also src/dst + dst-max atomic.
// Blocks [128, 128+129): e_time lookup table (+ table max atomic).
// ---------------------------------------------------------------------------
__global__ void __launch_bounds__(256)
prep_kernel(const float* __restrict__ feat,
            const float* __restrict__ a,
            const float* __restrict__ W,
            const int*   __restrict__ te,
            const float* __restrict__ bf) {
    const int warp = threadIdx.x >> 5;
    const int lane = threadIdx.x & 31;
    __shared__ float s_W[IN_DIM * OUT_DIM];      // 16 KB
    __shared__ float s_feat[16 * IN_DIM];        // 8 KB
    __shared__ float s_red[8];

    if (blockIdx.x < PREP_BLKS) {
        // Stage W (1024 x 16B) + feat tile (512 x 16B) in one async group.
#pragma unroll
        for (int t = 0; t < 4; ++t) {
            int seg = threadIdx.x + 256 * t;
            cp16((char*)s_W + seg * 16, (const char*)W + seg * 16);
        }
        {
            const char* fsrc = (const char*)(feat + blockIdx.x * 16 * IN_DIM);
#pragma unroll
            for (int t = 0; t < 2; ++t) {
                int seg = threadIdx.x + 256 * t;
                cp16((char*)s_feat + seg * 16, fsrc + seg * 16);
            }
        }
        CP_COMMIT();
        CP_WAIT0();
        __syncthreads();

        // Warp w computes rows 2w, 2w+1. Lane = output column.
        const int   r0 = 2 * warp;
        const float4* f0 = (const float4*)(s_feat + r0 * IN_DIM);
        const float4* f1 = (const float4*)(s_feat + (r0 + 1) * IN_DIM);
        float b00 = 0.f, b01 = 0.f, b10 = 0.f, b11 = 0.f;
#pragma unroll
        for (int d4 = 0; d4 < IN_DIM / 4; ++d4) {
            float4 x0 = f0[d4];                  // broadcast LDS.128
            float4 x1 = f1[d4];
            float w0 = s_W[(d4 * 4 + 0) * OUT_DIM + lane];  // bank = lane
            float w1 = s_W[(d4 * 4 + 1) * OUT_DIM + lane];
            float w2 = s_W[(d4 * 4 + 2) * OUT_DIM + lane];
            float w3 = s_W[(d4 * 4 + 3) * OUT_DIM + lane];
            b00 = fmaf(x0.x, w0, b00);  b01 = fmaf(x0.y, w1, b01);
            b00 = fmaf(x0.z, w2, b00);  b01 = fmaf(x0.w, w3, b01);
            b10 = fmaf(x1.x, w0, b10);  b11 = fmaf(x1.y, w1, b11);
            b10 = fmaf(x1.z, w2, b10);  b11 = fmaf(x1.w, w3, b11);
        }
        const float z0 = b00 + b01;
        const float z1 = b10 + b11;
        const int i0 = blockIdx.x * 16 + r0;
        g_z[(i0 + 0) * OUT_DIM + lane] = z0;
        g_z[(i0 + 1) * OUT_DIM + lane] = z1;

        // src/dst for both rows via butterfly reductions.
        const float a1 = a[lane], a2 = a[OUT_DIM + lane];
        float s0 = z0 * a1, t0 = z0 * a2;
        float s1 = z1 * a1, t1 = z1 * a2;
#pragma unroll
        for (int o = 16; o > 0; o >>= 1) {
            s0 += __shfl_xor_sync(0xffffffffu, s0, o);
            t0 += __shfl_xor_sync(0xffffffffu, t0, o);
            s1 += __shfl_xor_sync(0xffffffffu, s1, o);
            t1 += __shfl_xor_sync(0xffffffffu, t1, o);
        }
        if (lane == 0) {
            g_src[i0 + 0] = s0;  g_dst[i0 + 0] = t0;
            g_src[i0 + 1] = s1;  g_dst[i0 + 1] = t1;
            s_red[warp] = fmaxf(t0, t1);
        }
        __syncthreads();
        if (threadIdx.x == 0) {
            float md = s_red[0];
#pragma unroll
            for (int w = 1; w < 8; ++w) md = fmaxf(md, s_red[w]);
            atomicMaxFloat(&g_maxdst, md);
        }
    } else {
        // Table: warp w computes q; 8 q's per block.
        const int q = (blockIdx.x - PREP_BLKS) * 8 + warp;
        float v = -1e30f;
        if (q <= TABSZ) {
            int ti = *te;
            float T = (ti > -1000000 && ti < 1000000) ? (float)ti
                                                      : __int_as_float(ti);
            float tsv = (float)q / (float)TABSZ;
            float dt  = T - tsv;
            float th  = dt * bf[lane];
            v = a[2 * lane] * sinf(th) + a[2 * lane + 1] * cosf(th);
#pragma unroll
            for (int o = 16; o > 0; o >>= 1)
                v += __shfl_xor_sync(0xffffffffu, v, o);
            if (lane == 0) g_val[q] = v;
        }
        if (lane == 0) s_red[warp] = v;
        __syncthreads();
        if (threadIdx.x == 0) {
            float mg = s_red[0];
#pragma unroll
            for (int w = 1; w < 8; ++w) mg = fmaxf(mg, s_red[w]);
            atomicMaxFloat(&g_maxg, mg);
        }
    }
}

// ---------------------------------------------------------------------------
// Fused attention (exact R5 structure — best measured). grid = (NGROUPS, JSPLIT).
// Lane-parallel scores (lane = j); fixed softmax shift m_i (analytic upper
// bound -> exp in (0,1], no online rescale, branch-free). PV via smem-staged
// p tile read with broadcast LDS.128.
// ---------------------------------------------------------------------------
__global__ void __launch_bounds__(256)
attn_kernel(const int*   __restrict__ adj,
            const float* __restrict__ ts) {
    __shared__ float2 s_tab[TABSZ];                       // 8 KB
    __shared__ float  sm_p[NWARPS][32][ROWS];             // 8 KB
    __shared__ float  sm_l[ROWS][NWARPS];
    __shared__ float  sm_a[ROWS][NWARPS][OUT_DIM];        // 8 KB

    const int i0    = blockIdx.x * ROWS;
    const int split = blockIdx.y;
    const int jbase = split * JCHUNK;
    const int warp  = threadIdx.x >> 5;
    const int lane  = threadIdx.x & 31;

    for (int q = threadIdx.x; q < TABSZ; q += 256)
        s_tab[q] = make_float2(g_val[q], g_val[q + 1]);
    __syncthreads();

    const float MB = g_maxdst + g_maxg;
    float src[ROWS], m[ROWS], l[ROWS], acc[ROWS];
#pragma unroll
    for (int r = 0; r < ROWS; ++r) {
        src[r] = g_src[i0 + r];
        float U = src[r] + MB;
        m[r] = fmaxf(U, 0.05f * U);   // leaky of the raw upper bound
        l[r] = 0.f;  acc[r] = 0.f;
    }

    for (int bb = warp; bb < NBATCH; bb += NWARPS) {
        const int j = jbase + bb * 32 + lane;
        const float dstj = g_dst[j];
        float p[ROWS];
#pragma unroll
        for (int r = 0; r < ROWS; ++r) {
            const int   row = i0 + r;
            const int   av  = adj[row * N + j];
            const float t_  = ts [row * N + j];
            float qf = t_ * (float)TABSZ;          // ts in [0,1)
            int   qi = __float2int_rz(qf);
            float fr = qf - (float)qi;
            float2 tt = s_tab[qi];
            float g  = fmaf(fr, tt.y - tt.x, tt.x);
            float e  = src[r] + dstj + g;
            e = fmaxf(e, 0.05f * e);               // leaky relu
            e = (av > 0) ? (e - m[r]) : -1e30f;    // mask -> p = 0
            p[r] = __expf(e);
            l[r] += p[r];
        }
        // Stage p tile to smem: 2x STS.128 per lane
        float4* pd = (float4*)&sm_p[warp][lane][0];
        pd[0] = make_float4(p[0], p[1], p[2], p[3]);
        pd[1] = make_float4(p[4], p[5], p[6], p[7]);
        __syncwarp();

        const float* zb = g_z + (jbase + bb * 32) * OUT_DIM;
#pragma unroll
        for (int jj = 0; jj < 32; ++jj) {
            float zv = zb[jj * OUT_DIM + lane];    // coalesced 128B, L2-hit
            const float4* ps = (const float4*)&sm_p[warp][jj][0];
            float4 p03 = ps[0];                    // broadcast LDS.128
            float4 p47 = ps[1];
            acc[0] = fmaf(p03.x, zv, acc[0]);
            acc[1] = fmaf(p03.y, zv, acc[1]);
            acc[2] = fmaf(p03.z, zv, acc[2]);
            acc[3] = fmaf(p03.w, zv, acc[3]);
            acc[4] = fmaf(p47.x, zv, acc[4]);
            acc[5] = fmaf(p47.y, zv, acc[5]);
            acc[6] = fmaf(p47.z, zv, acc[6]);
            acc[7] = fmaf(p47.w, zv, acc[7]);
        }
        __syncwarp();
    }

    // Reduce l within warp; stash partials for cross-warp combine.
#pragma unroll
    for (int r = 0; r < ROWS; ++r) {
        float lv = l[r];
#pragma unroll
        for (int o = 16; o > 0; o >>= 1)
            lv += __shfl_xor_sync(0xffffffffu, lv, o);
        if (lane == 0) sm_l[r][warp] = lv;
        sm_a[r][warp][lane] = acc[r];
    }
    __syncthreads();

    // Warp r writes partial for row i0+r, this split.
    {
        const int r = warp;
        const int i = i0 + r;
        float L = 0.f, A = 0.f;
#pragma unroll
        for (int w = 0; w < NWARPS; ++w) {
            L += sm_l[r][w];
            A += sm_a[r][w][lane];
        }
        g_pa[(i * JSPLIT + split) * OUT_DIM + lane] = A;
        if (lane == 0) g_pl[i * JSPLIT + split] = L;
    }
}

// ---------------------------------------------------------------------------
// Combine partials + residual + layernorm. One warp per row.
// Also resets the max cells for the next graph replay.
// ---------------------------------------------------------------------------
__global__ void __launch_bounds__(256)
combine_kernel(const float* __restrict__ gamma,
               const float* __restrict__ beta,
               float*       __restrict__ out) {
    const int warp = threadIdx.x >> 5;
    const int lane = threadIdx.x & 31;
    const int i = blockIdx.x * 8 + warp;

    float A = 0.f, L = 0.f;
#pragma unroll
    for (int s = 0; s < JSPLIT; ++s) {
        A += g_pa[(i * JSPLIT + s) * OUT_DIM + lane];
        L += g_pl[i * JSPLIT + s];
    }
    float temp = A / L + g_z[i * OUT_DIM + lane];

    float mu = temp;
#pragma unroll
    for (int o = 16; o > 0; o >>= 1) mu += __shfl_xor_sync(0xffffffffu, mu, o);
    mu *= (1.0f / OUT_DIM);
    float d = temp - mu;
    float v = d * d;
#pragma unroll
    for (int o = 16; o > 0; o >>= 1) v += __shfl_xor_sync(0xffffffffu, v, o);
    v *= (1.0f / OUT_DIM);
    out[i * OUT_DIM + lane] = d * rsqrtf(v + 1e-6f) * gamma[lane] + beta[lane];

    if (blockIdx.x == 0 && threadIdx.x == 0) {
        g_maxdst = -1e30f;      // reset for next replay (deterministic)
        g_maxg   = -1e30f;
    }
}

// ---------------------------------------------------------------------------
extern "C" void kernel_launch(void* const* d_in, const int* in_sizes, int n_in,
                              void* d_out, int out_size) {
    const float* feat = (const float*)d_in[0];   // (2048,128) f32
    const int*   adj  = (const int*)  d_in[1];   // (2048,2048) i32
    const float* ts   = (const float*)d_in[2];   // (2048,2048) f32
    const float* a    = (const float*)d_in[3];   // (64,1) f32
    const int*   te   = (const int*)  d_in[4];   // scalar int
    const float* W    = (const float*)d_in[5];   // (128,32) f32
    const float* bf   = (const float*)d_in[6];   // (32,) f32
    const float* gam  = (const float*)d_in[7];   // (32,) f32
    const float* bet  = (const float*)d_in[8];   // (32,) f32
    float* out = (float*)d_out;                  // (2048,32) f32

    prep_kernel<<<PREP_BLKS + TAB_BLKS, 256>>>(feat, a, W, te, bf);
    dim3 grid(NGROUPS, JSPLIT);
    attn_kernel<<<grid, 256>>>(adj, ts);
    combine_kernel<<<N / 8, 256>>>(gam, bet, out);
}